// round 1
// baseline (speedup 1.0000x reference)
#include <cuda_runtime.h>

// Problem constants
#define BATCH 4096
#define FEAT  4096
#define NP    16
#define DDIM  256
#define MROWS (BATCH * NP)   // 65536
#define EPS   1e-5f
#define INV_SCALE 0.0625f    // 1/sqrt(256)

// ---------------- device scratch (no allocations allowed) ----------------
#define RCHUNKS 32
__device__ float g_psum[RCHUNKS * FEAT];
__device__ float g_psumsq[RCHUNKS * FEAT];
__device__ float g_scale[FEAT];   // rstd*gamma
__device__ float g_shift[FEAT];   // beta - mean*rstd*gamma
__device__ float g_xn[(size_t)BATCH * FEAT];    // 64 MB
__device__ float g_q[(size_t)MROWS * DDIM];     // 64 MB
__device__ float g_k[(size_t)MROWS * DDIM];     // 64 MB
__device__ float g_v[(size_t)MROWS * DDIM];     // 64 MB

// ---------------- BN pass 1: deterministic partial sums ----------------
// grid (FEAT/256, RCHUNKS), block 256. Each block: 256 cols x 128 rows.
__global__ void bn_pass1(const float* __restrict__ x) {
    int col = blockIdx.x * 256 + threadIdx.x;
    int r0  = blockIdx.y * (BATCH / RCHUNKS);
    float s = 0.f, ss = 0.f;
    #pragma unroll 4
    for (int r = 0; r < BATCH / RCHUNKS; r++) {
        float v = x[(size_t)(r0 + r) * FEAT + col];
        s += v; ss += v * v;
    }
    g_psum[blockIdx.y * FEAT + col]   = s;
    g_psumsq[blockIdx.y * FEAT + col] = ss;
}

// ---------------- BN pass 2: finalize affine ----------------
__global__ void bn_pass2(const float* __restrict__ gamma,
                         const float* __restrict__ beta) {
    int col = blockIdx.x * blockDim.x + threadIdx.x;
    float s = 0.f, ss = 0.f;
    #pragma unroll
    for (int c = 0; c < RCHUNKS; c++) {
        s  += g_psum[c * FEAT + col];
        ss += g_psumsq[c * FEAT + col];
    }
    float mean = s * (1.f / BATCH);
    float var  = ss * (1.f / BATCH) - mean * mean;
    float rstd = rsqrtf(var + EPS);
    float a = rstd * gamma[col];
    g_scale[col] = a;
    g_shift[col] = beta[col] - mean * a;
}

// ---------------- normalize: xn = x*a + b ----------------
__global__ void normalize_k(const float* __restrict__ x) {
    int i = blockIdx.x * blockDim.x + threadIdx.x;   // float4 index
    const float4* x4 = (const float4*)x;
    float4* o4 = (float4*)g_xn;
    int col = (i & (FEAT / 4 - 1)) * 4;
    float4 v = x4[i];
    v.x = v.x * g_scale[col + 0] + g_shift[col + 0];
    v.y = v.y * g_scale[col + 1] + g_shift[col + 1];
    v.z = v.z * g_scale[col + 2] + g_shift[col + 2];
    v.w = v.w * g_scale[col + 3] + g_shift[col + 3];
    o4[i] = v;
}

// ---------------- fused QKV GEMM: C[w] = xn @ W[w]^T + b[w] ----------------
// M=65536, N=256, K=256. BM=64, BN=64, BK=16. 256 threads, 4x4 per thread x3.
#define BM 64
#define BN 64
#define BK 16
__global__ void __launch_bounds__(256) gemm3(
    const float* __restrict__ wq, const float* __restrict__ bq,
    const float* __restrict__ wk, const float* __restrict__ bk,
    const float* __restrict__ wv, const float* __restrict__ bv)
{
    __shared__ float As[BK][BM];
    __shared__ float Bs[3][BK][BN];

    int m0 = blockIdx.y * BM;
    int n0 = blockIdx.x * BN;
    int tid = threadIdx.x;
    int tx = tid & 15;       // 0..15 -> n
    int ty = tid >> 4;       // 0..15 -> m

    float acc[3][4][4];
    #pragma unroll
    for (int w = 0; w < 3; w++)
        #pragma unroll
        for (int i = 0; i < 4; i++)
            #pragma unroll
            for (int j = 0; j < 4; j++) acc[w][i][j] = 0.f;

    int lrow = tid >> 2;          // 0..63
    int lk   = (tid & 3) * 4;     // 0,4,8,12

    for (int k0 = 0; k0 < DDIM; k0 += BK) {
        // A tile
        float4 a = *(const float4*)&g_xn[(size_t)(m0 + lrow) * DDIM + k0 + lk];
        As[lk + 0][lrow] = a.x; As[lk + 1][lrow] = a.y;
        As[lk + 2][lrow] = a.z; As[lk + 3][lrow] = a.w;
        // B tiles (W is [N][K] row-major; we need B[k][n] = W[n][k])
        float4 b0 = *(const float4*)&wq[(size_t)(n0 + lrow) * DDIM + k0 + lk];
        Bs[0][lk + 0][lrow] = b0.x; Bs[0][lk + 1][lrow] = b0.y;
        Bs[0][lk + 2][lrow] = b0.z; Bs[0][lk + 3][lrow] = b0.w;
        float4 b1 = *(const float4*)&wk[(size_t)(n0 + lrow) * DDIM + k0 + lk];
        Bs[1][lk + 0][lrow] = b1.x; Bs[1][lk + 1][lrow] = b1.y;
        Bs[1][lk + 2][lrow] = b1.z; Bs[1][lk + 3][lrow] = b1.w;
        float4 b2 = *(const float4*)&wv[(size_t)(n0 + lrow) * DDIM + k0 + lk];
        Bs[2][lk + 0][lrow] = b2.x; Bs[2][lk + 1][lrow] = b2.y;
        Bs[2][lk + 2][lrow] = b2.z; Bs[2][lk + 3][lrow] = b2.w;
        __syncthreads();

        #pragma unroll
        for (int k = 0; k < BK; k++) {
            float4 ra = *(const float4*)&As[k][ty * 4];
            float ar[4] = {ra.x, ra.y, ra.z, ra.w};
            #pragma unroll
            for (int w = 0; w < 3; w++) {
                float4 rb = *(const float4*)&Bs[w][k][tx * 4];
                float br[4] = {rb.x, rb.y, rb.z, rb.w};
                #pragma unroll
                for (int i = 0; i < 4; i++)
                    #pragma unroll
                    for (int j = 0; j < 4; j++)
                        acc[w][i][j] += ar[i] * br[j];
            }
        }
        __syncthreads();
    }

    // epilogue: add bias, store float4 rows
    float4 biasr[3];
    biasr[0] = *(const float4*)&bq[n0 + tx * 4];
    biasr[1] = *(const float4*)&bk[n0 + tx * 4];
    biasr[2] = *(const float4*)&bv[n0 + tx * 4];
    float* outs[3] = {g_q, g_k, g_v};
    #pragma unroll
    for (int w = 0; w < 3; w++) {
        #pragma unroll
        for (int i = 0; i < 4; i++) {
            float4 r;
            r.x = acc[w][i][0] + biasr[w].x;
            r.y = acc[w][i][1] + biasr[w].y;
            r.z = acc[w][i][2] + biasr[w].z;
            r.w = acc[w][i][3] + biasr[w].w;
            *(float4*)&outs[w][(size_t)(m0 + ty * 4 + i) * DDIM + n0 + tx * 4] = r;
        }
    }
}

// ---------------- per-batch attention (single-pass softmax, no max) -------
// block = one batch row b; 128 threads; each thread handles e and e+128.
__global__ void __launch_bounds__(128) attn_k(const float* __restrict__ x,
                                              float* __restrict__ out)
{
    __shared__ float Qs[NP * DDIM];   // [p][e] -- exactly the contiguous slice
    __shared__ float Ks[NP * DDIM];   // [p][f]
    __shared__ float Vs[NP * DDIM];   // [p][f]

    int b = blockIdx.x;
    int tid = threadIdx.x;

    {
        const float4* qsrc = (const float4*)(g_q + (size_t)b * (NP * DDIM));
        const float4* ksrc = (const float4*)(g_k + (size_t)b * (NP * DDIM));
        const float4* vsrc = (const float4*)(g_v + (size_t)b * (NP * DDIM));
        float4* qd = (float4*)Qs; float4* kd = (float4*)Ks; float4* vd = (float4*)Vs;
        #pragma unroll
        for (int i = tid; i < NP * DDIM / 4; i += 128) {
            qd[i] = qsrc[i]; kd[i] = ksrc[i]; vd[i] = vsrc[i];
        }
    }
    __syncthreads();

    int e0 = tid;          // handles e0 and e0 + 128
    float q0[NP], q1[NP];
    #pragma unroll
    for (int p = 0; p < NP; p++) {
        q0[p] = Qs[p * DDIM + e0];
        q1[p] = Qs[p * DDIM + e0 + 128];
    }
    float o0[NP], o1[NP];
    #pragma unroll
    for (int p = 0; p < NP; p++) { o0[p] = 0.f; o1[p] = 0.f; }
    float s0 = 0.f, s1 = 0.f;

    const float4* K4 = (const float4*)Ks;   // [p][f4], stride DDIM/4 = 64
    const float4* V4 = (const float4*)Vs;

    for (int f4 = 0; f4 < DDIM / 4; f4++) {
        float d00 = 0.f, d01 = 0.f, d02 = 0.f, d03 = 0.f;
        float d10 = 0.f, d11 = 0.f, d12 = 0.f, d13 = 0.f;
        #pragma unroll
        for (int p = 0; p < NP; p++) {
            float4 kk = K4[p * (DDIM / 4) + f4];      // broadcast
            d00 += q0[p] * kk.x; d01 += q0[p] * kk.y;
            d02 += q0[p] * kk.z; d03 += q0[p] * kk.w;
            d10 += q1[p] * kk.x; d11 += q1[p] * kk.y;
            d12 += q1[p] * kk.z; d13 += q1[p] * kk.w;
        }
        // dot values are bounded (|d*scale| < ~3): no max subtraction needed
        float t00 = __expf(d00 * INV_SCALE), t01 = __expf(d01 * INV_SCALE);
        float t02 = __expf(d02 * INV_SCALE), t03 = __expf(d03 * INV_SCALE);
        float t10 = __expf(d10 * INV_SCALE), t11 = __expf(d11 * INV_SCALE);
        float t12 = __expf(d12 * INV_SCALE), t13 = __expf(d13 * INV_SCALE);
        s0 += (t00 + t01) + (t02 + t03);
        s1 += (t10 + t11) + (t12 + t13);
        #pragma unroll
        for (int p = 0; p < NP; p++) {
            float4 vv = V4[p * (DDIM / 4) + f4];      // broadcast
            o0[p] += t00 * vv.x + t01 * vv.y + t02 * vv.z + t03 * vv.w;
            o1[p] += t10 * vv.x + t11 * vv.y + t12 * vv.z + t13 * vv.w;
        }
    }

    float inv0 = 1.f / s0, inv1 = 1.f / s1;
    // out[b, e*16+p] = o[p]/s + x[b, e*16+p]
    {
        size_t base = (size_t)b * FEAT + (size_t)e0 * NP;
        #pragma unroll
        for (int p4 = 0; p4 < 4; p4++) {
            float4 xr = *(const float4*)&x[base + p4 * 4];
            float4 r;
            r.x = o0[p4 * 4 + 0] * inv0 + xr.x;
            r.y = o0[p4 * 4 + 1] * inv0 + xr.y;
            r.z = o0[p4 * 4 + 2] * inv0 + xr.z;
            r.w = o0[p4 * 4 + 3] * inv0 + xr.w;
            *(float4*)&out[base + p4 * 4] = r;
        }
    }
    {
        size_t base = (size_t)b * FEAT + (size_t)(e0 + 128) * NP;
        #pragma unroll
        for (int p4 = 0; p4 < 4; p4++) {
            float4 xr = *(const float4*)&x[base + p4 * 4];
            float4 r;
            r.x = o1[p4 * 4 + 0] * inv1 + xr.x;
            r.y = o1[p4 * 4 + 1] * inv1 + xr.y;
            r.z = o1[p4 * 4 + 2] * inv1 + xr.z;
            r.w = o1[p4 * 4 + 3] * inv1 + xr.w;
            *(float4*)&out[base + p4 * 4] = r;
        }
    }
}

// ---------------- launcher ----------------
extern "C" void kernel_launch(void* const* d_in, const int* in_sizes, int n_in,
                              void* d_out, int out_size) {
    const float* x     = (const float*)d_in[0];
    const float* WQ_w  = (const float*)d_in[1];
    const float* WQ_b  = (const float*)d_in[2];
    const float* WK_w  = (const float*)d_in[3];
    const float* WK_b  = (const float*)d_in[4];
    const float* WV_w  = (const float*)d_in[5];
    const float* WV_b  = (const float*)d_in[6];
    const float* gamma = (const float*)d_in[7];
    const float* beta  = (const float*)d_in[8];
    float* out = (float*)d_out;

    bn_pass1<<<dim3(FEAT / 256, RCHUNKS), 256>>>(x);
    bn_pass2<<<FEAT / 256, 256>>>(gamma, beta);
    normalize_k<<<(BATCH * FEAT / 4) / 256, 256>>>(x);
    gemm3<<<dim3(DDIM / BN, MROWS / BM), 256>>>(WQ_w, WQ_b, WK_w, WK_b, WV_w, WV_b);
    attn_k<<<BATCH, 128>>>(x, out);
}